// round 14
// baseline (speedup 1.0000x reference)
#include <cuda_runtime.h>
#include <cuda_fp16.h>
#include <math.h>
#include <stdint.h>

#define BATCH 2
#define HDIM 192
#define WDIM 192
#define CDIM 192
#define WS 16
#define SHIFT 8
#define NH 6
#define HD 32
#define NTOK 256
#define NWSIDE 12
#define NWIN 144
#define TOTW 288
#define QKV_STRIDE (3*CDIM)

typedef unsigned long long u64;

// ---------------- scratch (no allocations allowed) ----------------
__device__ float g_cth[TOTW * NTOK];
__device__ float g_ctv[TOTW * NTOK];
__device__ float g_ao[(size_t)TOTW * NTOK * CDIM];

__device__ __forceinline__ int shifted_gaddr(int bi, int wh, int ww, int r, int c) {
    int hg = wh * WS + r + SHIFT; if (hg >= HDIM) hg -= HDIM;
    int wg = ww * WS + c + SHIFT; if (wg >= WDIM) wg -= WDIM;
    return (bi * HDIM + hg) * WDIM + wg;
}

// ---------------- f32x2 helpers (proj kernel) ----------------
__device__ __forceinline__ u64 ffma2(u64 a, u64 b, u64 c) {
    u64 d; asm("fma.rn.f32x2 %0, %1, %2, %3;" : "=l"(d) : "l"(a), "l"(b), "l"(c)); return d;
}
__device__ __forceinline__ float2 unpack2(u64 v) {
    float2 r; asm("mov.b64 {%0, %1}, %2;" : "=f"(r.x), "=f"(r.y) : "l"(v)); return r;
}

// ---------------- mma.sync helpers ----------------
__device__ __forceinline__ uint32_t smem_u32(const void* p) {
    uint32_t a;
    asm("{ .reg .u64 t; cvta.to.shared.u64 t, %1; cvt.u32.u64 %0, t; }" : "=r"(a) : "l"(p));
    return a;
}
__device__ __forceinline__ void ldsm4(uint32_t* r, uint32_t addr) {
    asm volatile("ldmatrix.sync.aligned.m8n8.x4.shared.b16 {%0,%1,%2,%3}, [%4];"
        : "=r"(r[0]), "=r"(r[1]), "=r"(r[2]), "=r"(r[3]) : "r"(addr));
}
__device__ __forceinline__ void mma_f16(float* d, const uint32_t* a, const uint32_t* b) {
    asm volatile("mma.sync.aligned.m16n8k16.row.col.f32.f16.f16.f32 "
        "{%0,%1,%2,%3}, {%4,%5,%6,%7}, {%8,%9}, {%0,%1,%2,%3};"
        : "+f"(d[0]), "+f"(d[1]), "+f"(d[2]), "+f"(d[3])
        : "r"(a[0]), "r"(a[1]), "r"(a[2]), "r"(a[3]), "r"(b[0]), "r"(b[1]));
}
__device__ __forceinline__ uint32_t packh2(float a, float b) {
    __half2 t = __floats2half2_rn(a, b);
    return *(uint32_t*)&t;
}
// Single-instruction MUFU exp2 regardless of compiler fast-math flags.
__device__ __forceinline__ float ex2(float x) {
    float r; asm("ex2.approx.f32 %0, %1;" : "=f"(r) : "f"(x)); return r;
}

// smem layout (bytes). Q/K planes: 256 rows x 80B (32 f16 + 16B pad).
// VT plane: 32 rows x 528B (256 f16 + 16B pad).
#define QKSTR 80
#define VTSTR 528
#define AT_QH 0
#define AT_KH 20480
#define AT_VH 40960
#define AT_R  57856
#define AT_CH 61700
#define AT_CV 62724
#define AT_RI 63748
#define AT_TOTAL 64772

#define L2E 1.4426950408889634f
#define FMAXB 8.0f

// ---------------------------------------------------------------------------
// Kernel 1: per-window geo cumsums ct_h, ct_v  (unchanged, known good)
// ---------------------------------------------------------------------------
__global__ void __launch_bounds__(512) geo_kernel(const float* __restrict__ x,
                                                  const float* __restrict__ sigma_p) {
    extern __shared__ float sf[];
    __shared__ float s_dh[16][16];
    __shared__ float s_dv[16][16];
    int b = blockIdx.x;
    int bi = b / NWIN, win = b - bi * NWIN;
    int wh = win / NWSIDE, ww = win - wh * NWSIDE;
    float sigma = fabsf(sigma_p[0]);

    const float4* x4 = (const float4*)x;
    float4* sf4 = (float4*)sf;
    for (int i = threadIdx.x; i < WS*WS*(CDIM/4); i += blockDim.x) {
        int pix = i / (CDIM/4);
        int c4  = i - pix*(CDIM/4);
        int g = shifted_gaddr(bi, wh, ww, pix >> 4, pix & 15);
        sf4[i] = x4[(size_t)g * (CDIM/4) + c4];
    }
    __syncthreads();

    int warp = threadIdx.x >> 5, lane = threadIdx.x & 31;
    for (int t = warp; t < 480; t += (blockDim.x >> 5)) {
        const float *p0, *p1;
        if (t < 240) {
            int r = t / 15, c = t - r*15;
            p0 = &sf[(r*WS + c)*CDIM]; p1 = p0 + CDIM;
        } else {
            int tt = t - 240;
            int c = tt / 15, r = tt - c*15;
            p0 = &sf[(r*WS + c)*CDIM]; p1 = p0 + WS*CDIM;
        }
        float s = 0.f;
        for (int ch = lane; ch < CDIM; ch += 32) s += fabsf(p1[ch] - p0[ch]);
        #pragma unroll
        for (int off = 16; off; off >>= 1) s += __shfl_down_sync(0xffffffffu, s, off);
        if (lane == 0) {
            if (t < 240) { int r = t/15, c = t - r*15; s_dh[r][c] = s; }
            else { int tt = t - 240; int c = tt/15, r = tt - c*15; s_dv[c][r] = s; }
        }
    }
    __syncthreads();

    if (threadIdx.x < 16) {
        int r = threadIdx.x;
        float acc = 0.f;
        g_cth[b*NTOK + r*WS] = 0.f;
        for (int c = 1; c < WS; c++) {
            acc += 1.0f + sigma * s_dh[r][c-1];
            g_cth[b*NTOK + r*WS + c] = acc;
        }
    } else if (threadIdx.x < 32) {
        int c = threadIdx.x - 16;
        float acc = 0.f;
        g_ctv[b*NTOK + c] = 0.f;
        for (int r = 1; r < WS; r++) {
            acc += 1.0f + sigma * s_dv[c][r-1];
            g_ctv[b*NTOK + r*WS + c] = acc;
        }
    }
}

// ---------------------------------------------------------------------------
// Kernel 2: attention per (window, head), mma.sync f16, single-pass QK and PV.
// Q pre-scaled by qscale*log2e (S in log2 domain). ex2.approx epilogue.
// 16-col chunks; V-ldsm hoisted above the bias epilogue. Fixed max = 8.
// ---------------------------------------------------------------------------
__global__ void __launch_bounds__(512, 2) attn_kernel(const float* __restrict__ qkv,
                                                      const float* __restrict__ rpb_table,
                                                      const float* __restrict__ geo_scale) {
    extern __shared__ char smc[];
    uint32_t sb = smem_u32(smc);
    float* sR  = (float*)(smc + AT_R);
    float* sCH = (float*)(smc + AT_CH);
    float* sCV = (float*)(smc + AT_CV);
    int*   sRI = (int*)(smc + AT_RI);

    int head = blockIdx.x, b = blockIdx.y;
    int bi = b / NWIN, win = b - bi*NWIN;
    int wh = win / NWSIDE, ww = win - wh*NWSIDE;
    int tid = threadIdx.x, wid = tid >> 5, lane = tid & 31;

    // ---- stage Q/K (f16, K-major) and V^T (f16), plus tables ----
    const float qscale = 0.17677669529663687f * L2E;   // 32^-0.5 * log2e
    for (int i = tid; i < NTOK*HD; i += 512) {
        int tok = i >> 5, d = i & 31;
        int g = shifted_gaddr(bi, wh, ww, tok >> 4, tok & 15);
        const float* base = qkv + (size_t)g * QKV_STRIDE + head * HD + d;
        int qko = tok*QKSTR + d*2;
        *(unsigned short*)(smc + AT_QH + qko) =
            __half_as_ushort(__float2half_rn(base[0] * qscale));
        *(unsigned short*)(smc + AT_KH + qko) =
            __half_as_ushort(__float2half_rn(base[CDIM]));
        *(unsigned short*)(smc + AT_VH + d*VTSTR + tok*2) =
            __half_as_ushort(__float2half_rn(base[2*CDIM]));
    }
    for (int i = tid; i < 961; i += 512)
        sR[i] = (rpb_table[i * NH + head] - FMAXB) * L2E;
    if (tid < 256) {
        sCH[tid] = g_cth[b*NTOK + tid];
        sCV[tid] = g_ctv[b*NTOK + tid];
        int r = tid >> 4, c = tid & 15;
        int hg = wh*WS + r, wg = ww*WS + c;
        int rh = (hg < HDIM - WS) ? 0 : ((hg < HDIM - SHIFT) ? 1 : 2);
        int rw = (wg < WDIM - WS) ? 0 : ((wg < WDIM - SHIFT) ? 1 : 2);
        sRI[tid] = rh * 3 + rw;
    }
    __syncthreads();

    int m = wid * 16;                 // this warp's query rows [m, m+16)
    int gid = lane >> 2, tig = lane & 3;
    int rowA = m + gid, rowB = rowA + 8;
    bool masked = (wh >= 10) || (ww >= 10);   // interior windows: uniform region id

    // ---- Q fragments (hoisted) ----
    uint32_t qh[2][4];
    {
        int arow = m + (lane & 7) + ((lane & 8) ? 8 : 0);
        int acol = (lane & 16) ? 8 : 0;
        #pragma unroll
        for (int kk = 0; kk < 2; kk++)
            ldsm4(qh[kk], sb + AT_QH + (uint32_t)(arow*QKSTR + (kk*16 + acol)*2));
    }

    // ---- per-thread bias constants ----
    float ngscl = -geo_scale[head] * L2E;
    float cthqA = sCH[rowA], cthqB = sCH[rowB];
    int ridA = sRI[rowA], ridB = sRI[rowB];
    int baseqA = (m >> 4)*31 + gid + 480;
    float ghA[4], ghB[4];
    #pragma unroll
    for (int xi = 0; xi < 4; xi++) {
        int ck = (xi >> 1)*8 + tig*2 + (xi & 1);
        float chv = sCH[m + ck];
        ghA[xi] = fabsf(chv - cthqA);
        ghB[xi] = fabsf(chv - cthqB);
    }

    int krow = (lane & 7) + ((lane & 16) ? 8 : 0);
    int kcol = (lane & 8) ? 8 : 0;
    int vrow = (lane & 7) + ((lane & 16) ? 8 : 0);
    int vtok = (lane & 8) ? 8 : 0;

    float O[4][4];
    #pragma unroll
    for (int j = 0; j < 4; j++)
        #pragma unroll
        for (int e = 0; e < 4; e++) O[j][e] = 0.f;
    float lsumA = 0.f, lsumB = 0.f;

    #pragma unroll 1
    for (int nb = 0; nb < 16; nb++) {          // 16-column (16-token) chunks
        int cb = nb * 16;
        float S[2][4];
        #pragma unroll
        for (int j = 0; j < 2; j++)
            #pragma unroll
            for (int e = 0; e < 4; e++) S[j][e] = 0.f;

        // ---- S = Q K^T over this 16-col chunk (single-pass f16) ----
        #pragma unroll
        for (int kk = 0; kk < 2; kk++) {
            uint32_t off = (uint32_t)((cb + krow)*QKSTR + (kk*16 + kcol)*2);
            uint32_t kh[4];
            ldsm4(kh, sb + AT_KH + off);
            mma_f16(S[0], qh[kk], &kh[0]);
            mma_f16(S[1], qh[kk], &kh[2]);
        }

        // ---- V fragments: independent of S — hoist above the epilogue so the
        // LDSM latency overlaps the bias/exp computation. ----
        uint32_t vh0[4], vh1[4];
        ldsm4(vh0, sb + AT_VH + (uint32_t)((vrow)*VTSTR + (cb + vtok)*2));
        ldsm4(vh1, sb + AT_VH + (uint32_t)((16 + vrow)*VTSTR + (cb + vtok)*2));

        // ---- bias + ex2 (fixed max 8); S already in log2 units ----
        int rbase = baseqA - nb*31;
        #pragma unroll
        for (int j = 0; j < 2; j++) {
            #pragma unroll
            for (int e = 0; e < 2; e++) {
                int xi = j*2 + e;
                int ck = j*8 + tig*2 + e;
                int col = cb + ck;
                float gv = fabsf(sCV[col] - sCV[m + ck]);
                int idx = rbase - ck;
                float argA = fmaf(ghA[xi] + gv, ngscl, sR[idx]);
                float argB = fmaf(ghB[xi] + gv, ngscl, sR[idx + 8]);
                if (masked) {
                    int ridc = sRI[col];
                    if (ridc != ridA) argA -= 100.f * L2E;
                    if (ridc != ridB) argB -= 100.f * L2E;
                }
                float pA = ex2(S[j][e] + argA);
                float pB = ex2(S[j][e + 2] + argB);
                lsumA += pA; lsumB += pB;
                S[j][e] = pA; S[j][e + 2] = pB;
            }
        }

        // ---- P f16 A-fragment for this 16-token chunk ----
        uint32_t phi[4];
        phi[0] = packh2(S[0][0], S[0][1]);
        phi[1] = packh2(S[0][2], S[0][3]);
        phi[2] = packh2(S[1][0], S[1][1]);
        phi[3] = packh2(S[1][2], S[1][3]);

        // ---- O += P V (single-pass) ----
        mma_f16(O[0], phi, &vh0[0]);
        mma_f16(O[1], phi, &vh0[2]);
        mma_f16(O[2], phi, &vh1[0]);
        mma_f16(O[3], phi, &vh1[2]);
    }

    // ---- normalize + store ----
    lsumA += __shfl_xor_sync(0xffffffffu, lsumA, 1);
    lsumA += __shfl_xor_sync(0xffffffffu, lsumA, 2);
    lsumB += __shfl_xor_sync(0xffffffffu, lsumB, 1);
    lsumB += __shfl_xor_sync(0xffffffffu, lsumB, 2);
    float liA = 1.f / lsumA, liB = 1.f / lsumB;

    float* dA = g_ao + ((size_t)b*NTOK + rowA)*CDIM + head*HD;
    float* dB = g_ao + ((size_t)b*NTOK + rowB)*CDIM + head*HD;
    #pragma unroll
    for (int j = 0; j < 4; j++) {
        int col = j*8 + tig*2;
        *(float2*)(dA + col) = make_float2(O[j][0]*liA, O[j][1]*liA);
        *(float2*)(dB + col) = make_float2(O[j][2]*liB, O[j][3]*liB);
    }
}

// ---------------------------------------------------------------------------
// Kernel 3: out = AO @ W^T + b (f32x2), scattered through window_reverse+roll
// ---------------------------------------------------------------------------
#define PSTR 196

__global__ void __launch_bounds__(256) proj_kernel(const float* __restrict__ proj_w,
                                                   const float* __restrict__ proj_b,
                                                   float* __restrict__ out) {
    extern __shared__ float sm[];
    float* sW = sm;
    float* sA = sm + CDIM * PSTR;
    int b  = blockIdx.y;
    int pb = blockIdx.x * 64;
    int bi = b / NWIN, win = b - bi*NWIN;
    int wh = win / NWSIDE, ww = win - wh*NWSIDE;
    int tid = threadIdx.x;

    for (int i = tid; i < CDIM*CDIM; i += 256) {
        int o = i / CDIM, ii = i - o*CDIM;
        sW[o*PSTR + ii] = proj_w[i];
    }
    for (int i = tid; i < 64*CDIM; i += 256) {
        int p = i / CDIM, ii = i - p*CDIM;
        sA[p*PSTR + ii] = g_ao[((size_t)b*NTOK + pb + p)*CDIM + ii];
    }
    __syncthreads();

    int pg = tid >> 4, og = tid & 15;
    u64 acc2[4][12];
    #pragma unroll
    for (int a = 0; a < 4; a++)
        #pragma unroll
        for (int j = 0; j < 12; j++) acc2[a][j] = 0ull;

    #pragma unroll 1
    for (int ii = 0; ii < CDIM; ii += 4) {
        ulonglong2 av[4];
        #pragma unroll
        for (int a = 0; a < 4; a++)
            av[a] = *(const ulonglong2*)&sA[(pg*4 + a)*PSTR + ii];
        #pragma unroll
        for (int j = 0; j < 12; j++) {
            ulonglong2 wv = *(const ulonglong2*)&sW[(og + 16*j)*PSTR + ii];
            #pragma unroll
            for (int a = 0; a < 4; a++) {
                acc2[a][j] = ffma2(av[a].x, wv.x, acc2[a][j]);
                acc2[a][j] = ffma2(av[a].y, wv.y, acc2[a][j]);
            }
        }
    }

    #pragma unroll
    for (int j = 0; j < 12; j++) {
        int o = og + 16*j;
        float bv = proj_b[o];
        #pragma unroll
        for (int a = 0; a < 4; a++) {
            int n = pb + pg*4 + a;
            int r = n >> 4, c = n & 15;
            int ho = wh*WS + r + SHIFT; if (ho >= HDIM) ho -= HDIM;
            int wo = ww*WS + c + SHIFT; if (wo >= WDIM) wo -= WDIM;
            float2 t = unpack2(acc2[a][j]);
            out[(((size_t)bi*HDIM + ho)*WDIM + wo)*CDIM + o] = t.x + t.y + bv;
        }
    }
}

// ---------------------------------------------------------------------------
extern "C" void kernel_launch(void* const* d_in, const int* in_sizes, int n_in,
                              void* d_out, int out_size) {
    const float* x         = (const float*)d_in[0];
    const float* qkv       = (const float*)d_in[1];
    const float* rpb_table = (const float*)d_in[2];
    const float* geo_scale = (const float*)d_in[3];
    const float* geo_sigma = (const float*)d_in[4];
    const float* proj_w    = (const float*)d_in[5];
    const float* proj_b    = (const float*)d_in[6];
    float* out = (float*)d_out;

    int geo_smem  = WS*WS*CDIM*4;
    int attn_smem = AT_TOTAL;
    int proj_smem = (CDIM*PSTR + 64*PSTR) * 4;

    cudaFuncSetAttribute(geo_kernel,  cudaFuncAttributeMaxDynamicSharedMemorySize, geo_smem);
    cudaFuncSetAttribute(attn_kernel, cudaFuncAttributeMaxDynamicSharedMemorySize, attn_smem);
    cudaFuncSetAttribute(proj_kernel, cudaFuncAttributeMaxDynamicSharedMemorySize, proj_smem);

    geo_kernel<<<TOTW, 512, geo_smem>>>(x, geo_sigma);
    attn_kernel<<<dim3(NH, TOTW), 512, attn_smem>>>(qkv, rpb_table, geo_scale);
    proj_kernel<<<dim3(4, TOTW), 256, proj_smem>>>(proj_w, proj_b, out);
}

// round 15
// speedup vs baseline: 1.1188x; 1.1188x over previous
#include <cuda_runtime.h>
#include <cuda_fp16.h>
#include <math.h>
#include <stdint.h>

#define BATCH 2
#define HDIM 192
#define WDIM 192
#define CDIM 192
#define WS 16
#define SHIFT 8
#define NH 6
#define HD 32
#define NTOK 256
#define NWSIDE 12
#define NWIN 144
#define TOTW 288
#define QKV_STRIDE (3*CDIM)

typedef unsigned long long u64;

// ---------------- scratch (no allocations allowed) ----------------
__device__ float g_cth[TOTW * NTOK];
__device__ float g_ctv[TOTW * NTOK];
__device__ float g_ao[(size_t)TOTW * NTOK * CDIM];

__device__ __forceinline__ int shifted_gaddr(int bi, int wh, int ww, int r, int c) {
    int hg = wh * WS + r + SHIFT; if (hg >= HDIM) hg -= HDIM;
    int wg = ww * WS + c + SHIFT; if (wg >= WDIM) wg -= WDIM;
    return (bi * HDIM + hg) * WDIM + wg;
}

// ---------------- f32x2 helpers (proj kernel) ----------------
__device__ __forceinline__ u64 ffma2(u64 a, u64 b, u64 c) {
    u64 d; asm("fma.rn.f32x2 %0, %1, %2, %3;" : "=l"(d) : "l"(a), "l"(b), "l"(c)); return d;
}
__device__ __forceinline__ float2 unpack2(u64 v) {
    float2 r; asm("mov.b64 {%0, %1}, %2;" : "=f"(r.x), "=f"(r.y) : "l"(v)); return r;
}

// ---------------- mma.sync helpers ----------------
__device__ __forceinline__ uint32_t smem_u32(const void* p) {
    uint32_t a;
    asm("{ .reg .u64 t; cvta.to.shared.u64 t, %1; cvt.u32.u64 %0, t; }" : "=r"(a) : "l"(p));
    return a;
}
__device__ __forceinline__ void ldsm4(uint32_t* r, uint32_t addr) {
    asm volatile("ldmatrix.sync.aligned.m8n8.x4.shared.b16 {%0,%1,%2,%3}, [%4];"
        : "=r"(r[0]), "=r"(r[1]), "=r"(r[2]), "=r"(r[3]) : "r"(addr));
}
__device__ __forceinline__ void mma_f16(float* d, const uint32_t* a, const uint32_t* b) {
    asm volatile("mma.sync.aligned.m16n8k16.row.col.f32.f16.f16.f32 "
        "{%0,%1,%2,%3}, {%4,%5,%6,%7}, {%8,%9}, {%0,%1,%2,%3};"
        : "+f"(d[0]), "+f"(d[1]), "+f"(d[2]), "+f"(d[3])
        : "r"(a[0]), "r"(a[1]), "r"(a[2]), "r"(a[3]), "r"(b[0]), "r"(b[1]));
}
__device__ __forceinline__ uint32_t packh2(float a, float b) {
    __half2 t = __floats2half2_rn(a, b);
    return *(uint32_t*)&t;
}
__device__ __forceinline__ float ex2(float x) {
    float r; asm("ex2.approx.f32 %0, %1;" : "=f"(r) : "f"(x)); return r;
}

// smem layout (bytes). Q/K planes: 256 rows x 80B (32 f16 + 16B pad).
// VT plane: 32 rows x 528B (256 f16 + 16B pad).
#define QKSTR 80
#define VTSTR 528
#define AT_QH 0
#define AT_KH 20480
#define AT_VH 40960
#define AT_R  57856
#define AT_CH 61700
#define AT_CV 62724
#define AT_RI 63748
#define AT_TOTAL 64772

#define L2E 1.4426950408889634f
#define FMAXB 8.0f

// ---------------------------------------------------------------------------
// Kernel 1: per-window geo cumsums ct_h, ct_v (1024 threads for latency hiding)
// ---------------------------------------------------------------------------
__global__ void __launch_bounds__(1024) geo_kernel(const float* __restrict__ x,
                                                   const float* __restrict__ sigma_p) {
    extern __shared__ float sf[];
    __shared__ float s_dh[16][16];
    __shared__ float s_dv[16][16];
    int b = blockIdx.x;
    int bi = b / NWIN, win = b - bi * NWIN;
    int wh = win / NWSIDE, ww = win - wh * NWSIDE;
    float sigma = fabsf(sigma_p[0]);

    const float4* x4 = (const float4*)x;
    float4* sf4 = (float4*)sf;
    for (int i = threadIdx.x; i < WS*WS*(CDIM/4); i += blockDim.x) {
        int pix = i / (CDIM/4);
        int c4  = i - pix*(CDIM/4);
        int g = shifted_gaddr(bi, wh, ww, pix >> 4, pix & 15);
        sf4[i] = x4[(size_t)g * (CDIM/4) + c4];
    }
    __syncthreads();

    int warp = threadIdx.x >> 5, lane = threadIdx.x & 31;
    for (int t = warp; t < 480; t += (blockDim.x >> 5)) {
        const float *p0, *p1;
        if (t < 240) {
            int r = t / 15, c = t - r*15;
            p0 = &sf[(r*WS + c)*CDIM]; p1 = p0 + CDIM;
        } else {
            int tt = t - 240;
            int c = tt / 15, r = tt - c*15;
            p0 = &sf[(r*WS + c)*CDIM]; p1 = p0 + WS*CDIM;
        }
        float s = 0.f;
        for (int ch = lane; ch < CDIM; ch += 32) s += fabsf(p1[ch] - p0[ch]);
        #pragma unroll
        for (int off = 16; off; off >>= 1) s += __shfl_down_sync(0xffffffffu, s, off);
        if (lane == 0) {
            if (t < 240) { int r = t/15, c = t - r*15; s_dh[r][c] = s; }
            else { int tt = t - 240; int c = tt/15, r = tt - c*15; s_dv[c][r] = s; }
        }
    }
    __syncthreads();

    if (threadIdx.x < 16) {
        int r = threadIdx.x;
        float acc = 0.f;
        g_cth[b*NTOK + r*WS] = 0.f;
        for (int c = 1; c < WS; c++) {
            acc += 1.0f + sigma * s_dh[r][c-1];
            g_cth[b*NTOK + r*WS + c] = acc;
        }
    } else if (threadIdx.x < 32) {
        int c = threadIdx.x - 16;
        float acc = 0.f;
        g_ctv[b*NTOK + c] = 0.f;
        for (int r = 1; r < WS; r++) {
            acc += 1.0f + sigma * s_dv[c][r-1];
            g_ctv[b*NTOK + r*WS + c] = acc;
        }
    }
}

// ---------------------------------------------------------------------------
// Kernel 2: attention per (window, head), mma.sync f16 single-pass QK/PV.
// Software-pipelined: K fragments for chunk nb+1 prefetched during chunk nb's
// epilogue. Q pre-scaled by qscale*log2e; ex2 epilogue; fixed max = 8.
// ---------------------------------------------------------------------------
__global__ void __launch_bounds__(512, 2) attn_kernel(const float* __restrict__ qkv,
                                                      const float* __restrict__ rpb_table,
                                                      const float* __restrict__ geo_scale) {
    extern __shared__ char smc[];
    uint32_t sb = smem_u32(smc);
    float* sR  = (float*)(smc + AT_R);
    float* sCH = (float*)(smc + AT_CH);
    float* sCV = (float*)(smc + AT_CV);
    int*   sRI = (int*)(smc + AT_RI);

    int head = blockIdx.x, b = blockIdx.y;
    int bi = b / NWIN, win = b - bi*NWIN;
    int wh = win / NWSIDE, ww = win - wh*NWSIDE;
    int tid = threadIdx.x, wid = tid >> 5, lane = tid & 31;

    // ---- stage Q/K (f16, K-major) and V^T (f16), vectorized ----
    const float qscale = 0.17677669529663687f * L2E;   // 32^-0.5 * log2e
    for (int i = tid; i < NTOK*16; i += 512) {
        int tok = i >> 4, d2 = (i & 15) << 1;
        int g = shifted_gaddr(bi, wh, ww, tok >> 4, tok & 15);
        const float* base = qkv + (size_t)g * QKV_STRIDE + head * HD + d2;
        float2 q2 = *(const float2*)base;
        float2 k2 = *(const float2*)(base + CDIM);
        float2 v2 = *(const float2*)(base + 2*CDIM);
        int qko = tok*QKSTR + d2*2;
        *(uint32_t*)(smc + AT_QH + qko) = packh2(q2.x*qscale, q2.y*qscale);
        *(uint32_t*)(smc + AT_KH + qko) = packh2(k2.x, k2.y);
        *(unsigned short*)(smc + AT_VH + d2*VTSTR + tok*2) =
            __half_as_ushort(__float2half_rn(v2.x));
        *(unsigned short*)(smc + AT_VH + (d2+1)*VTSTR + tok*2) =
            __half_as_ushort(__float2half_rn(v2.y));
    }
    for (int i = tid; i < 961; i += 512)
        sR[i] = (rpb_table[i * NH + head] - FMAXB) * L2E;
    if (tid < 256) {
        sCH[tid] = g_cth[b*NTOK + tid];
        sCV[tid] = g_ctv[b*NTOK + tid];
        int r = tid >> 4, c = tid & 15;
        int hg = wh*WS + r, wg = ww*WS + c;
        int rh = (hg < HDIM - WS) ? 0 : ((hg < HDIM - SHIFT) ? 1 : 2);
        int rw = (wg < WDIM - WS) ? 0 : ((wg < WDIM - SHIFT) ? 1 : 2);
        sRI[tid] = rh * 3 + rw;
    }
    __syncthreads();

    int m = wid * 16;                 // this warp's query rows [m, m+16)
    int gid = lane >> 2, tig = lane & 3;
    int rowA = m + gid, rowB = rowA + 8;
    bool masked = (wh >= 10) || (ww >= 10);

    // ---- Q fragments (hoisted) ----
    uint32_t qh[2][4];
    {
        int arow = m + (lane & 7) + ((lane & 8) ? 8 : 0);
        int acol = (lane & 16) ? 8 : 0;
        #pragma unroll
        for (int kk = 0; kk < 2; kk++)
            ldsm4(qh[kk], sb + AT_QH + (uint32_t)(arow*QKSTR + (kk*16 + acol)*2));
    }

    // ---- per-thread bias constants (arrays dropped; recomputed from smem) ----
    float ngscl = -geo_scale[head] * L2E;
    float cthqA = sCH[rowA], cthqB = sCH[rowB];
    int ridA = sRI[rowA], ridB = sRI[rowB];
    int baseqA = (m >> 4)*31 + gid + 480;

    int krow = (lane & 7) + ((lane & 16) ? 8 : 0);
    int kcol = (lane & 8) ? 8 : 0;
    int vrow = (lane & 7) + ((lane & 16) ? 8 : 0);
    int vtok = (lane & 8) ? 8 : 0;
    uint32_t kbase = sb + AT_KH + (uint32_t)(krow*QKSTR + kcol*2);
    uint32_t vbase = sb + AT_VH + (uint32_t)(vrow*VTSTR + vtok*2);

    float O[4][4];
    #pragma unroll
    for (int j = 0; j < 4; j++)
        #pragma unroll
        for (int e = 0; e < 4; e++) O[j][e] = 0.f;
    float lsumA = 0.f, lsumB = 0.f;

    // ---- prime the K pipeline (chunk 0) ----
    uint32_t kh0[4], kh1[4];
    ldsm4(kh0, kbase);
    ldsm4(kh1, kbase + 32);

    #pragma unroll 1
    for (int nb = 0; nb < 16; nb++) {
        int cb = nb * 16;
        float S[2][4];
        #pragma unroll
        for (int j = 0; j < 2; j++)
            #pragma unroll
            for (int e = 0; e < 4; e++) S[j][e] = 0.f;

        // ---- S = Q K^T for this chunk (fragments already resident) ----
        mma_f16(S[0], qh[0], &kh0[0]);
        mma_f16(S[1], qh[0], &kh0[2]);
        mma_f16(S[0], qh[1], &kh1[0]);
        mma_f16(S[1], qh[1], &kh1[2]);

        // ---- prefetch next chunk's K: latency overlaps the epilogue ----
        if (nb < 15) {
            uint32_t koff = kbase + (uint32_t)((cb + 16)*QKSTR);
            ldsm4(kh0, koff);
            ldsm4(kh1, koff + 32);
        }
        // ---- V fragments (independent of S) ----
        uint32_t vh0[4], vh1[4];
        ldsm4(vh0, vbase + (uint32_t)(cb*2));
        ldsm4(vh1, vbase + (uint32_t)(16*VTSTR + cb*2));

        // ---- bias + ex2 (fixed max 8); S already in log2 units ----
        int rbase = baseqA - nb*31;
        #pragma unroll
        for (int j = 0; j < 2; j++) {
            #pragma unroll
            for (int e = 0; e < 2; e++) {
                int ck = j*8 + tig*2 + e;
                int col = cb + ck;
                float chv = sCH[m + ck];
                float gv = fabsf(sCV[col] - sCV[m + ck]);
                int idx = rbase - ck;
                float argA = fmaf(fabsf(chv - cthqA) + gv, ngscl, sR[idx]);
                float argB = fmaf(fabsf(chv - cthqB) + gv, ngscl, sR[idx + 8]);
                if (masked) {
                    int ridc = sRI[col];
                    if (ridc != ridA) argA -= 100.f * L2E;
                    if (ridc != ridB) argB -= 100.f * L2E;
                }
                float pA = ex2(S[j][e] + argA);
                float pB = ex2(S[j][e + 2] + argB);
                lsumA += pA; lsumB += pB;
                S[j][e] = pA; S[j][e + 2] = pB;
            }
        }

        // ---- P f16 A-fragment ----
        uint32_t phi[4];
        phi[0] = packh2(S[0][0], S[0][1]);
        phi[1] = packh2(S[0][2], S[0][3]);
        phi[2] = packh2(S[1][0], S[1][1]);
        phi[3] = packh2(S[1][2], S[1][3]);

        // ---- O += P V ----
        mma_f16(O[0], phi, &vh0[0]);
        mma_f16(O[1], phi, &vh0[2]);
        mma_f16(O[2], phi, &vh1[0]);
        mma_f16(O[3], phi, &vh1[2]);
    }

    // ---- normalize + store ----
    lsumA += __shfl_xor_sync(0xffffffffu, lsumA, 1);
    lsumA += __shfl_xor_sync(0xffffffffu, lsumA, 2);
    lsumB += __shfl_xor_sync(0xffffffffu, lsumB, 1);
    lsumB += __shfl_xor_sync(0xffffffffu, lsumB, 2);
    float liA = 1.f / lsumA, liB = 1.f / lsumB;

    float* dA = g_ao + ((size_t)b*NTOK + rowA)*CDIM + head*HD;
    float* dB = g_ao + ((size_t)b*NTOK + rowB)*CDIM + head*HD;
    #pragma unroll
    for (int j = 0; j < 4; j++) {
        int col = j*8 + tig*2;
        *(float2*)(dA + col) = make_float2(O[j][0]*liA, O[j][1]*liA);
        *(float2*)(dB + col) = make_float2(O[j][2]*liB, O[j][3]*liB);
    }
}

// ---------------------------------------------------------------------------
// Kernel 3: out = AO @ W^T + b (f32x2), scattered through window_reverse+roll
// ---------------------------------------------------------------------------
#define PSTR 196

__global__ void __launch_bounds__(256) proj_kernel(const float* __restrict__ proj_w,
                                                   const float* __restrict__ proj_b,
                                                   float* __restrict__ out) {
    extern __shared__ float sm[];
    float* sW = sm;
    float* sA = sm + CDIM * PSTR;
    int b  = blockIdx.y;
    int pb = blockIdx.x * 64;
    int bi = b / NWIN, win = b - bi*NWIN;
    int wh = win / NWSIDE, ww = win - wh*NWSIDE;
    int tid = threadIdx.x;

    for (int i = tid; i < CDIM*CDIM; i += 256) {
        int o = i / CDIM, ii = i - o*CDIM;
        sW[o*PSTR + ii] = proj_w[i];
    }
    for (int i = tid; i < 64*CDIM; i += 256) {
        int p = i / CDIM, ii = i - p*CDIM;
        sA[p*PSTR + ii] = g_ao[((size_t)b*NTOK + pb + p)*CDIM + ii];
    }
    __syncthreads();

    int pg = tid >> 4, og = tid & 15;
    u64 acc2[4][12];
    #pragma unroll
    for (int a = 0; a < 4; a++)
        #pragma unroll
        for (int j = 0; j < 12; j++) acc2[a][j] = 0ull;

    #pragma unroll 2
    for (int ii = 0; ii < CDIM; ii += 4) {
        ulonglong2 av[4];
        #pragma unroll
        for (int a = 0; a < 4; a++)
            av[a] = *(const ulonglong2*)&sA[(pg*4 + a)*PSTR + ii];
        #pragma unroll
        for (int j = 0; j < 12; j++) {
            ulonglong2 wv = *(const ulonglong2*)&sW[(og + 16*j)*PSTR + ii];
            #pragma unroll
            for (int a = 0; a < 4; a++) {
                acc2[a][j] = ffma2(av[a].x, wv.x, acc2[a][j]);
                acc2[a][j] = ffma2(av[a].y, wv.y, acc2[a][j]);
            }
        }
    }

    #pragma unroll
    for (int j = 0; j < 12; j++) {
        int o = og + 16*j;
        float bv = proj_b[o];
        #pragma unroll
        for (int a = 0; a < 4; a++) {
            int n = pb + pg*4 + a;
            int r = n >> 4, c = n & 15;
            int ho = wh*WS + r + SHIFT; if (ho >= HDIM) ho -= HDIM;
            int wo = ww*WS + c + SHIFT; if (wo >= WDIM) wo -= WDIM;
            float2 t = unpack2(acc2[a][j]);
            out[(((size_t)bi*HDIM + ho)*WDIM + wo)*CDIM + o] = t.x + t.y + bv;
        }
    }
}

// ---------------------------------------------------------------------------
extern "C" void kernel_launch(void* const* d_in, const int* in_sizes, int n_in,
                              void* d_out, int out_size) {
    const float* x         = (const float*)d_in[0];
    const float* qkv       = (const float*)d_in[1];
    const float* rpb_table = (const float*)d_in[2];
    const float* geo_scale = (const float*)d_in[3];
    const float* geo_sigma = (const float*)d_in[4];
    const float* proj_w    = (const float*)d_in[5];
    const float* proj_b    = (const float*)d_in[6];
    float* out = (float*)d_out;

    int geo_smem  = WS*WS*CDIM*4;
    int attn_smem = AT_TOTAL;
    int proj_smem = (CDIM*PSTR + 64*PSTR) * 4;

    cudaFuncSetAttribute(geo_kernel,  cudaFuncAttributeMaxDynamicSharedMemorySize, geo_smem);
    cudaFuncSetAttribute(attn_kernel, cudaFuncAttributeMaxDynamicSharedMemorySize, attn_smem);
    cudaFuncSetAttribute(proj_kernel, cudaFuncAttributeMaxDynamicSharedMemorySize, proj_smem);

    geo_kernel<<<TOTW, 1024, geo_smem>>>(x, geo_sigma);
    attn_kernel<<<dim3(NH, TOTW), 512, attn_smem>>>(qkv, rpb_table, geo_scale);
    proj_kernel<<<dim3(4, TOTW), 256, proj_smem>>>(proj_w, proj_b, out);
}